// round 16
// baseline (speedup 1.0000x reference)
#include <cuda_runtime.h>
#include <cuda_fp16.h>
#include <cstdint>
#include <math.h>

// Problem constants
#define B_SZ 4
#define T_SZ 2048
#define DM   1024
#define NH   16
#define HD   64
#define MROWS (B_SZ * T_SZ)   // 8192
#define NELEM (MROWS * DM)

#define PERSIST_CTAS 296      // 2 CTAs/SM * 148 SMs

// ---------------- scratch (allocation-free) ----------------
__device__ __half g_xh[NELEM];
__device__ __half g_oh[NELEM];
__device__ __half g_qh[NELEM];
__device__ __half g_kh[NELEM];
__device__ __half g_vh[NELEM];
__device__ __half g_wq[DM * DM];
__device__ __half g_wk[DM * DM];
__device__ __half g_wv[DM * DM];
__device__ __half g_wo[DM * DM];

// ---------------- helpers ----------------
__device__ __forceinline__ uint32_t smem_u32(const void* p) {
    uint32_t a;
    asm("{ .reg .u64 t; cvta.to.shared.u64 t, %1; cvt.u32.u64 %0, t; }" : "=r"(a) : "l"(p));
    return a;
}

#define LDSM_X4(r, addr) \
    asm volatile("ldmatrix.sync.aligned.m8n8.x4.shared.b16 {%0,%1,%2,%3}, [%4];" \
        : "=r"((r)[0]), "=r"((r)[1]), "=r"((r)[2]), "=r"((r)[3]) : "r"(addr))

#define LDSM_X4_T(r, addr) \
    asm volatile("ldmatrix.sync.aligned.m8n8.x4.trans.shared.b16 {%0,%1,%2,%3}, [%4];" \
        : "=r"((r)[0]), "=r"((r)[1]), "=r"((r)[2]), "=r"((r)[3]) : "r"(addr))

#define MMA_F16(d, a, b0, b1) \
    asm volatile("mma.sync.aligned.m16n8k16.row.col.f32.f16.f16.f32 " \
        "{%0,%1,%2,%3}, {%4,%5,%6,%7}, {%8,%9}, {%0,%1,%2,%3};" \
        : "+f"((d)[0]), "+f"((d)[1]), "+f"((d)[2]), "+f"((d)[3]) \
        : "r"((a)[0]), "r"((a)[1]), "r"((a)[2]), "r"((a)[3]), "r"(b0), "r"(b1))

#define CP_ASYNC16(saddr, gptr) \
    asm volatile("cp.async.cg.shared.global [%0], [%1], 16;" :: "r"(saddr), "l"(gptr))
#define CP_COMMIT() asm volatile("cp.async.commit_group;" ::: "memory")
#define CP_WAIT0()  asm volatile("cp.async.wait_group 0;" ::: "memory")

__device__ __forceinline__ uint32_t pack_h2(float a, float b) {
    __half2 h = __floats2half2_rn(a, b);   // low = a, high = b
    return *(uint32_t*)&h;
}

// ---------------- fp32 -> fp16 convert kernels ----------------
__global__ __launch_bounds__(256)
void cvt_kernel(const float* __restrict__ src, __half* __restrict__ dst, int n4)
{
    int i = blockIdx.x * blockDim.x + threadIdx.x;
    if (i >= n4) return;
    float4 v = ((const float4*)src)[i];
    ((uint32_t*)dst)[2*i]   = pack_h2(v.x, v.y);
    ((uint32_t*)dst)[2*i+1] = pack_h2(v.z, v.w);
}

__global__ __launch_bounds__(256)
void cvtw_kernel(const float* __restrict__ W0, const float* __restrict__ W1,
                 const float* __restrict__ W2, const float* __restrict__ W3, int n4)
{
    int i = blockIdx.x * blockDim.x + threadIdx.x;
    if (i >= n4) return;
    const int z = blockIdx.z;
    const float* src = (z == 0) ? W0 : (z == 1) ? W1 : (z == 2) ? W2 : W3;
    __half* dst = (z == 0) ? g_wq : (z == 1) ? g_wk : (z == 2) ? g_wv : g_wo;
    float4 v = ((const float4*)src)[i];
    ((uint32_t*)dst)[2*i]   = pack_h2(v.x, v.y);
    ((uint32_t*)dst)[2*i+1] = pack_h2(v.z, v.w);
}

// ---------------- fp16 NT GEMM (persistent, 1 sync/chunk) ----------------
#define GBM 128
#define GBN 128
#define GBK 64
#define OPB (GBM * GBK * 2)       // 16384
#define OFF_A 0
#define OFF_B OPB
#define G_STAGE (2 * OPB)         // 32768
#define GEMM_SMEM (2 * G_STAGE)   // 65536

__device__ __forceinline__ uint32_t fsw(int r, int c) {   // 128B-row swizzle
    return (uint32_t)(r * 128 + ((c ^ (r & 7)) << 4));
}

__device__ __forceinline__ void gemm_prefetch(
    uint32_t stage_base, const __half* A, const __half* B,
    int row0, int col0, int koff, int tid)
{
    const int cc = tid & 7;
    const int rr0 = tid >> 3;   // 0..31
    #pragma unroll
    for (int i = 0; i < 4; ++i) {
        const int rr = rr0 + i * 32;
        const uint32_t so = fsw(rr, cc);
        CP_ASYNC16(stage_base + OFF_A + so, A + (size_t)(row0 + rr) * DM + koff + cc * 8);
        CP_ASYNC16(stage_base + OFF_B + so, B + (size_t)(col0 + rr) * DM + koff + cc * 8);
    }
}

// One 128x128 tile. If Ch != nullptr: fp16 out (cscale*acc); else fp32 C (+bias).
__device__ __forceinline__ void gemm_item(
    const __half* __restrict__ A, const __half* __restrict__ B,
    float* __restrict__ C, const float* __restrict__ bias,
    __half* __restrict__ Ch, float cscale, int row0, int col0, char* smem)
{
    const uint32_t sb = smem_u32(smem);
    const int tid  = threadIdx.x;
    const int warp = tid >> 5;
    const int lane = tid & 31;
    const int wm = warp & 1;
    const int wn = warp >> 1;

    float acc[4][4][4];
    #pragma unroll
    for (int a = 0; a < 4; ++a)
        #pragma unroll
        for (int b = 0; b < 4; ++b)
            #pragma unroll
            for (int c = 0; c < 4; ++c) acc[a][b][c] = 0.f;

    const int sub = lane >> 3;
    const int l7  = lane & 7;
    const int nchunk = DM / GBK;   // 16

    gemm_prefetch(sb, A, B, row0, col0, 0, tid);
    CP_COMMIT();

    for (int kc = 0; kc < nchunk; ++kc) {
        CP_WAIT0();
        __syncthreads();
        if (kc + 1 < nchunk) {
            gemm_prefetch(sb + ((kc + 1) & 1) * G_STAGE, A, B, row0, col0, (kc + 1) * GBK, tid);
            CP_COMMIT();
        }
        const uint32_t ss = sb + (kc & 1) * G_STAGE;
        #pragma unroll
        for (int ks = 0; ks < 4; ++ks) {
            uint32_t af[4][4], bf[4][2];
            #pragma unroll
            for (int mt = 0; mt < 4; ++mt) {
                const int r  = wm * 64 + mt * 16 + ((sub & 1) << 3) + l7;
                const int ch = ks * 2 + (sub >> 1);
                LDSM_X4(af[mt], ss + OFF_A + fsw(r, ch));
            }
            #pragma unroll
            for (int np = 0; np < 2; ++np) {
                const int r  = wn * 32 + np * 16 + ((sub >> 1) << 3) + l7;
                const int ch = ks * 2 + (sub & 1);
                uint32_t t[4];
                LDSM_X4(t, ss + OFF_B + fsw(r, ch));
                bf[np*2][0]   = t[0]; bf[np*2][1]   = t[1];
                bf[np*2+1][0] = t[2]; bf[np*2+1][1] = t[3];
            }
            #pragma unroll
            for (int mt = 0; mt < 4; ++mt)
                #pragma unroll
                for (int nt = 0; nt < 4; ++nt)
                    MMA_F16(acc[mt][nt], af[mt], bf[nt][0], bf[nt][1]);
        }
    }

    const int er = lane >> 2;
    const int ec = (lane & 3) * 2;
    if (Ch) {
        #pragma unroll
        for (int mt = 0; mt < 4; ++mt) {
            const int grow = row0 + wm * 64 + mt * 16 + er;
            #pragma unroll
            for (int nt = 0; nt < 4; ++nt) {
                const int gcol = col0 + wn * 32 + nt * 8 + ec;
                *(uint32_t*)&Ch[(size_t)grow * DM + gcol] =
                    pack_h2(acc[mt][nt][0] * cscale, acc[mt][nt][1] * cscale);
                *(uint32_t*)&Ch[(size_t)(grow + 8) * DM + gcol] =
                    pack_h2(acc[mt][nt][2] * cscale, acc[mt][nt][3] * cscale);
            }
        }
    } else {
        #pragma unroll
        for (int mt = 0; mt < 4; ++mt) {
            const int grow = row0 + wm * 64 + mt * 16 + er;
            #pragma unroll
            for (int nt = 0; nt < 4; ++nt) {
                const int gcol = col0 + wn * 32 + nt * 8 + ec;
                float bx = bias[gcol], by = bias[gcol + 1];
                *(float2*)&C[(size_t)grow * DM + gcol] =
                    make_float2(acc[mt][nt][0] + bx, acc[mt][nt][1] + by);
                *(float2*)&C[(size_t)(grow + 8) * DM + gcol] =
                    make_float2(acc[mt][nt][2] + bx, acc[mt][nt][3] + by);
            }
        }
    }
}

// Persistent fused Q/K/V projection: 1536 items (z * 512 + by*8 + bx).
__global__ __launch_bounds__(256, 2)
void gemm_qkv_kernel(const __half* __restrict__ xh, float qscale)
{
    extern __shared__ __align__(128) char smem[];
    for (int it = blockIdx.x; it < 1536; it += gridDim.x) {
        const int z = it / 512;
        const int r = it % 512;
        const int row0 = (r >> 3) * GBM;
        const int col0 = (r & 7) * GBN;
        const __half* B = (z == 0) ? g_wq : (z == 1) ? g_wk : g_wv;
        __half* Ch = (z == 0) ? g_qh : (z == 1) ? g_kh : g_vh;
        const float cs = (z == 0) ? qscale : 1.0f;
        gemm_item(xh, B, nullptr, nullptr, Ch, cs, row0, col0, smem);
    }
}

// Persistent output projection: 512 items.
__global__ __launch_bounds__(256, 2)
void gemm_out_kernel(const __half* __restrict__ Ah, float* __restrict__ C,
                     const float* __restrict__ bias)
{
    extern __shared__ __align__(128) char smem[];
    for (int it = blockIdx.x; it < 512; it += gridDim.x) {
        const int row0 = (it >> 3) * GBM;
        const int col0 = (it & 7) * GBN;
        gemm_item(Ah, g_wo, C, bias, nullptr, 1.0f, row0, col0, smem);
    }
}

// ---------------- persistent fp16 flash attention ----------------
#define FA_BN 64
#define FA_TILEB (FA_BN * 128)        // 8192
#define FA_STAGE (2 * FA_TILEB)       // 16384: K | V
#define FA_SMEM (2 * FA_STAGE)        // 32768
#define FA_ITEMS ((T_SZ / 128) * NH * B_SZ)   // 1024

__device__ __forceinline__ void attn_prefetch(
    uint32_t stage_base, const __half* K, const __half* V,
    size_t rowbase, int colbase, int key0, int tid)
{
    #pragma unroll
    for (int i = 0; i < 2; ++i) {
        int u = tid + i * 256;
        int r = u >> 3, c = u & 7;
        const size_t g = (rowbase + key0 + r) * DM + colbase + c * 8;
        const uint32_t so = fsw(r, c);
        CP_ASYNC16(stage_base + so,            K + g);
        CP_ASYNC16(stage_base + FA_TILEB + so, V + g);
    }
}

__global__ __launch_bounds__(256, 2)
void attn_mma_kernel(const __half* __restrict__ Q, const __half* __restrict__ K,
                     const __half* __restrict__ V, __half* __restrict__ O)
{
    extern __shared__ __align__(128) char sm[];
    const uint32_t sb = smem_u32(sm);

    const int tid  = threadIdx.x;
    const int warp = tid >> 5;
    const int lane = tid & 31;
    const int sub  = lane >> 3;
    const int l7   = lane & 7;

    for (int item = blockIdx.x; item < FA_ITEMS; item += gridDim.x) {
        const int qi = item & 15;             // q-tile
        const int h  = (item >> 4) & 15;      // head
        const int b  = item >> 8;             // batch
        const int q0 = qi * 128;
        const size_t rowbase = (size_t)b * T_SZ;
        const int    colbase = h * HD;

        // stage Q tile through buffer 0, keep A fragments
        uint32_t qf[4][4];
        {
            #pragma unroll
            for (int i = 0; i < 4; ++i) {
                int u = tid + i * 256;
                int r = u >> 3, c = u & 7;
                const uint4 v = *(const uint4*)(Q + (rowbase + q0 + r) * DM + colbase + c * 8);
                *(uint4*)(sm + fsw(r, c)) = v;
            }
            __syncthreads();
            #pragma unroll
            for (int t = 0; t < 4; ++t) {
                const int r  = warp * 16 + ((sub & 1) << 3) + l7;
                const int ch = t * 2 + (sub >> 1);
                LDSM_X4(qf[t], sb + fsw(r, ch));
            }
            __syncthreads();
        }

        float acc[8][4];
        #pragma unroll
        for (int j = 0; j < 8; ++j)
            #pragma unroll
            for (int c = 0; c < 4; ++c) acc[j][c] = 0.f;
        float m0 = -1e30f, m1 = -1e30f, l0 = 0.f, l1 = 0.f;

        attn_prefetch(sb, K, V, rowbase, colbase, 0, tid);
        CP_COMMIT();

        const int ntiles = T_SZ / FA_BN;   // 32
        for (int kt = 0; kt < ntiles; ++kt) {
            CP_WAIT0();
            __syncthreads();
            if (kt + 1 < ntiles) {
                attn_prefetch(sb + ((kt + 1) & 1) * FA_STAGE, K, V, rowbase, colbase, (kt + 1) * FA_BN, tid);
                CP_COMMIT();
            }
            const uint32_t ss = sb + (kt & 1) * FA_STAGE;

            // S = Q K^T
            float st[8][4];
            #pragma unroll
            for (int j = 0; j < 8; ++j)
                #pragma unroll
                for (int c = 0; c < 4; ++c) st[j][c] = 0.f;

            #pragma unroll
            for (int np = 0; np < 4; ++np) {
                #pragma unroll
                for (int t = 0; t < 4; ++t) {
                    const int r  = np * 16 + ((sub >> 1) << 3) + l7;
                    const int ch = t * 2 + (sub & 1);
                    uint32_t e[4];
                    LDSM_X4(e, ss + fsw(r, ch));
                    MMA_F16(st[np*2],   qf[t], e[0], e[1]);
                    MMA_F16(st[np*2+1], qf[t], e[2], e[3]);
                }
            }

            // running max (log2 domain; Q pre-scaled by 0.125*log2e)
            float tm0 = st[0][0], tm1 = st[0][2];
            #pragma unroll
            for (int j = 0; j < 8; ++j) {
                tm0 = fmaxf(tm0, fmaxf(st[j][0], st[j][1]));
                tm1 = fmaxf(tm1, fmaxf(st[j][2], st[j][3]));
            }
            tm0 = fmaxf(tm0, __shfl_xor_sync(0xffffffffu, tm0, 1));
            tm0 = fmaxf(tm0, __shfl_xor_sync(0xffffffffu, tm0, 2));
            tm1 = fmaxf(tm1, __shfl_xor_sync(0xffffffffu, tm1, 1));
            tm1 = fmaxf(tm1, __shfl_xor_sync(0xffffffffu, tm1, 2));
            const float nm0 = fmaxf(m0, tm0), nm1 = fmaxf(m1, tm1);
            const float c0 = exp2f(m0 - nm0), c1 = exp2f(m1 - nm1);
            m0 = nm0; m1 = nm1;
            if (__any_sync(0xffffffffu, (c0 != 1.f) | (c1 != 1.f))) {
                l0 *= c0; l1 *= c1;
                #pragma unroll
                for (int j = 0; j < 8; ++j) {
                    acc[j][0] *= c0; acc[j][1] *= c0;
                    acc[j][2] *= c1; acc[j][3] *= c1;
                }
            }

            // exp2 + pack + PV, interleaved per 16-key chunk
            #pragma unroll
            for (int t = 0; t < 4; ++t) {
                float e00 = exp2f(st[2*t][0]   - m0);
                float e01 = exp2f(st[2*t][1]   - m0);
                float e02 = exp2f(st[2*t][2]   - m1);
                float e03 = exp2f(st[2*t][3]   - m1);
                float e10 = exp2f(st[2*t+1][0] - m0);
                float e11 = exp2f(st[2*t+1][1] - m0);
                float e12 = exp2f(st[2*t+1][2] - m1);
                float e13 = exp2f(st[2*t+1][3] - m1);
                l0 += e00 + e01 + e10 + e11;
                l1 += e02 + e03 + e12 + e13;
                uint32_t pf[4];
                pf[0] = pack_h2(e00, e01);
                pf[1] = pack_h2(e02, e03);
                pf[2] = pack_h2(e10, e11);
                pf[3] = pack_h2(e12, e13);
                #pragma unroll
                for (int dp = 0; dp < 4; ++dp) {
                    const int r  = t * 16 + ((sub & 1) << 3) + l7;
                    const int ch = dp * 2 + (sub >> 1);
                    uint32_t v[4];
                    LDSM_X4_T(v, ss + FA_TILEB + fsw(r, ch));
                    MMA_F16(acc[dp*2],   pf, v[0], v[1]);
                    MMA_F16(acc[dp*2+1], pf, v[2], v[3]);
                }
            }
        }

        // finalize, write fp16 O
        float s0 = l0, s1 = l1;
        s0 += __shfl_xor_sync(0xffffffffu, s0, 1);
        s0 += __shfl_xor_sync(0xffffffffu, s0, 2);
        s1 += __shfl_xor_sync(0xffffffffu, s1, 1);
        s1 += __shfl_xor_sync(0xffffffffu, s1, 2);
        const float inv0 = 1.f / (s0 + 1e-8f);
        const float inv1 = 1.f / (s1 + 1e-8f);

        const int r0 = q0 + warp * 16 + (lane >> 2);
        const int ec = (lane & 3) * 2;
        #pragma unroll
        for (int j = 0; j < 8; ++j) {
            const int gcol = colbase + j * 8 + ec;
            *(uint32_t*)&O[(rowbase + r0) * DM + gcol] =
                pack_h2(acc[j][0] * inv0, acc[j][1] * inv0);
            *(uint32_t*)&O[(rowbase + r0 + 8) * DM + gcol] =
                pack_h2(acc[j][2] * inv1, acc[j][3] * inv1);
        }
        __syncthreads();   // all warps done with smem before next item's Q staging
    }
}

// ---------------- launch ----------------
extern "C" void kernel_launch(void* const* d_in, const int* in_sizes, int n_in,
                              void* d_out, int out_size)
{
    const float* x  = (const float*)d_in[0];
    const float* Wq = (const float*)d_in[1];
    const float* Wk = (const float*)d_in[2];
    const float* Wv = (const float*)d_in[3];
    const float* Wo = (const float*)d_in[4];
    const float* bo = (const float*)d_in[5];
    float* out = (float*)d_out;

    __half *xh, *oh, *qh, *kh, *vh;
    cudaGetSymbolAddress((void**)&xh, g_xh);
    cudaGetSymbolAddress((void**)&oh, g_oh);
    cudaGetSymbolAddress((void**)&qh, g_qh);
    cudaGetSymbolAddress((void**)&kh, g_kh);
    cudaGetSymbolAddress((void**)&vh, g_vh);

    cudaFuncSetAttribute(gemm_qkv_kernel, cudaFuncAttributeMaxDynamicSharedMemorySize, GEMM_SMEM);
    cudaFuncSetAttribute(gemm_out_kernel, cudaFuncAttributeMaxDynamicSharedMemorySize, GEMM_SMEM);
    cudaFuncSetAttribute(attn_mma_kernel, cudaFuncAttributeMaxDynamicSharedMemorySize, FA_SMEM);

    const int n4x = NELEM / 4;
    const int n4w = (DM * DM) / 4;
    cvt_kernel<<<n4x / 256, 256>>>(x, xh, n4x);
    dim3 wgrid(n4w / 256, 1, 4);
    cvtw_kernel<<<wgrid, 256>>>(Wq, Wk, Wv, Wo, n4w);

    const float qscale = 0.125f * 1.44269504088896341f;   // (1/sqrt(64)) * log2(e)
    gemm_qkv_kernel<<<PERSIST_CTAS, 256, GEMM_SMEM>>>(xh, qscale);
    attn_mma_kernel<<<PERSIST_CTAS, 256, FA_SMEM>>>(qh, kh, vh, oh);
    gemm_out_kernel<<<PERSIST_CTAS, 256, GEMM_SMEM>>>(oh, out, bo);
}

// round 17
// speedup vs baseline: 1.0042x; 1.0042x over previous
#include <cuda_runtime.h>
#include <cuda_fp16.h>
#include <cstdint>
#include <math.h>

// Problem constants
#define B_SZ 4
#define T_SZ 2048
#define DM   1024
#define NH   16
#define HD   64
#define MROWS (B_SZ * T_SZ)   // 8192
#define NELEM (MROWS * DM)

#define PERSIST_CTAS 296      // 2 CTAs/SM * 148 SMs

// ---------------- scratch (allocation-free) ----------------
__device__ __half g_xh[NELEM];
__device__ __half g_oh[NELEM];
__device__ __half g_qh[NELEM];
__device__ __half g_kh[NELEM];
__device__ __half g_vh[NELEM];
__device__ __half g_wq[DM * DM];
__device__ __half g_wk[DM * DM];
__device__ __half g_wv[DM * DM];
__device__ __half g_wo[DM * DM];

// ---------------- helpers ----------------
__device__ __forceinline__ uint32_t smem_u32(const void* p) {
    uint32_t a;
    asm("{ .reg .u64 t; cvta.to.shared.u64 t, %1; cvt.u32.u64 %0, t; }" : "=r"(a) : "l"(p));
    return a;
}

#define LDSM_X4(r, addr) \
    asm volatile("ldmatrix.sync.aligned.m8n8.x4.shared.b16 {%0,%1,%2,%3}, [%4];" \
        : "=r"((r)[0]), "=r"((r)[1]), "=r"((r)[2]), "=r"((r)[3]) : "r"(addr))

#define LDSM_X4_T(r, addr) \
    asm volatile("ldmatrix.sync.aligned.m8n8.x4.trans.shared.b16 {%0,%1,%2,%3}, [%4];" \
        : "=r"((r)[0]), "=r"((r)[1]), "=r"((r)[2]), "=r"((r)[3]) : "r"(addr))

#define MMA_F16(d, a, b0, b1) \
    asm volatile("mma.sync.aligned.m16n8k16.row.col.f32.f16.f16.f32 " \
        "{%0,%1,%2,%3}, {%4,%5,%6,%7}, {%8,%9}, {%0,%1,%2,%3};" \
        : "+f"((d)[0]), "+f"((d)[1]), "+f"((d)[2]), "+f"((d)[3]) \
        : "r"((a)[0]), "r"((a)[1]), "r"((a)[2]), "r"((a)[3]), "r"(b0), "r"(b1))

#define CP_ASYNC16(saddr, gptr) \
    asm volatile("cp.async.cg.shared.global [%0], [%1], 16;" :: "r"(saddr), "l"(gptr))
#define CP_COMMIT() asm volatile("cp.async.commit_group;" ::: "memory")
#define CP_WAIT0()  asm volatile("cp.async.wait_group 0;" ::: "memory")
#define CP_WAIT1()  asm volatile("cp.async.wait_group 1;" ::: "memory")

__device__ __forceinline__ uint32_t pack_h2(float a, float b) {
    __half2 h = __floats2half2_rn(a, b);   // low = a, high = b
    return *(uint32_t*)&h;
}

// ---------------- fp32 -> fp16 convert kernels ----------------
__global__ __launch_bounds__(256)
void cvt_kernel(const float* __restrict__ src, __half* __restrict__ dst, int n4)
{
    int i = blockIdx.x * blockDim.x + threadIdx.x;
    if (i >= n4) return;
    float4 v = ((const float4*)src)[i];
    ((uint32_t*)dst)[2*i]   = pack_h2(v.x, v.y);
    ((uint32_t*)dst)[2*i+1] = pack_h2(v.z, v.w);
}

__global__ __launch_bounds__(256)
void cvtw_kernel(const float* __restrict__ W0, const float* __restrict__ W1,
                 const float* __restrict__ W2, const float* __restrict__ W3, int n4)
{
    int i = blockIdx.x * blockDim.x + threadIdx.x;
    if (i >= n4) return;
    const int z = blockIdx.z;
    const float* src = (z == 0) ? W0 : (z == 1) ? W1 : (z == 2) ? W2 : W3;
    __half* dst = (z == 0) ? g_wq : (z == 1) ? g_wk : (z == 2) ? g_wv : g_wo;
    float4 v = ((const float4*)src)[i];
    ((uint32_t*)dst)[2*i]   = pack_h2(v.x, v.y);
    ((uint32_t*)dst)[2*i+1] = pack_h2(v.z, v.w);
}

// ---------------- fp16 NT GEMM (persistent) ----------------
#define GBM 128
#define GBN 128
#define GBK 64
#define OPB (GBM * GBK * 2)       // 16384
#define OFF_A 0
#define OFF_B OPB
#define G_STAGE (2 * OPB)         // 32768
#define GEMM_SMEM (2 * G_STAGE)   // 65536

__device__ __forceinline__ uint32_t fsw(int r, int c) {   // 128B-row swizzle
    return (uint32_t)(r * 128 + ((c ^ (r & 7)) << 4));
}

__device__ __forceinline__ void gemm_prefetch(
    uint32_t stage_base, const __half* A, const __half* B,
    int row0, int col0, int koff, int tid)
{
    const int cc = tid & 7;
    const int rr0 = tid >> 3;   // 0..31
    #pragma unroll
    for (int i = 0; i < 4; ++i) {
        const int rr = rr0 + i * 32;
        const uint32_t so = fsw(rr, cc);
        CP_ASYNC16(stage_base + OFF_A + so, A + (size_t)(row0 + rr) * DM + koff + cc * 8);
        CP_ASYNC16(stage_base + OFF_B + so, B + (size_t)(col0 + rr) * DM + koff + cc * 8);
    }
}

// One 128x128 tile. If Ch != nullptr: fp16 out (cscale*acc); else fp32 C (+bias).
__device__ __forceinline__ void gemm_item(
    const __half* __restrict__ A, const __half* __restrict__ B,
    float* __restrict__ C, const float* __restrict__ bias,
    __half* __restrict__ Ch, float cscale, int row0, int col0, char* smem)
{
    const uint32_t sb = smem_u32(smem);
    const int tid  = threadIdx.x;
    const int warp = tid >> 5;
    const int lane = tid & 31;
    const int wm = warp & 1;
    const int wn = warp >> 1;

    float acc[4][4][4];
    #pragma unroll
    for (int a = 0; a < 4; ++a)
        #pragma unroll
        for (int b = 0; b < 4; ++b)
            #pragma unroll
            for (int c = 0; c < 4; ++c) acc[a][b][c] = 0.f;

    const int sub = lane >> 3;
    const int l7  = lane & 7;
    const int nchunk = DM / GBK;   // 16

    gemm_prefetch(sb, A, B, row0, col0, 0, tid);
    CP_COMMIT();

    for (int kc = 0; kc < nchunk; ++kc) {
        CP_WAIT0();
        __syncthreads();
        if (kc + 1 < nchunk) {
            gemm_prefetch(sb + ((kc + 1) & 1) * G_STAGE, A, B, row0, col0, (kc + 1) * GBK, tid);
            CP_COMMIT();
        }
        const uint32_t ss = sb + (kc & 1) * G_STAGE;
        #pragma unroll
        for (int ks = 0; ks < 4; ++ks) {
            uint32_t af[4][4], bf[4][2];
            #pragma unroll
            for (int mt = 0; mt < 4; ++mt) {
                const int r  = wm * 64 + mt * 16 + ((sub & 1) << 3) + l7;
                const int ch = ks * 2 + (sub >> 1);
                LDSM_X4(af[mt], ss + OFF_A + fsw(r, ch));
            }
            #pragma unroll
            for (int np = 0; np < 2; ++np) {
                const int r  = wn * 32 + np * 16 + ((sub >> 1) << 3) + l7;
                const int ch = ks * 2 + (sub & 1);
                uint32_t t[4];
                LDSM_X4(t, ss + OFF_B + fsw(r, ch));
                bf[np*2][0]   = t[0]; bf[np*2][1]   = t[1];
                bf[np*2+1][0] = t[2]; bf[np*2+1][1] = t[3];
            }
            #pragma unroll
            for (int mt = 0; mt < 4; ++mt)
                #pragma unroll
                for (int nt = 0; nt < 4; ++nt)
                    MMA_F16(acc[mt][nt], af[mt], bf[nt][0], bf[nt][1]);
        }
    }

    const int er = lane >> 2;
    const int ec = (lane & 3) * 2;
    if (Ch) {
        #pragma unroll
        for (int mt = 0; mt < 4; ++mt) {
            const int grow = row0 + wm * 64 + mt * 16 + er;
            #pragma unroll
            for (int nt = 0; nt < 4; ++nt) {
                const int gcol = col0 + wn * 32 + nt * 8 + ec;
                *(uint32_t*)&Ch[(size_t)grow * DM + gcol] =
                    pack_h2(acc[mt][nt][0] * cscale, acc[mt][nt][1] * cscale);
                *(uint32_t*)&Ch[(size_t)(grow + 8) * DM + gcol] =
                    pack_h2(acc[mt][nt][2] * cscale, acc[mt][nt][3] * cscale);
            }
        }
    } else {
        #pragma unroll
        for (int mt = 0; mt < 4; ++mt) {
            const int grow = row0 + wm * 64 + mt * 16 + er;
            #pragma unroll
            for (int nt = 0; nt < 4; ++nt) {
                const int gcol = col0 + wn * 32 + nt * 8 + ec;
                float bx = bias[gcol], by = bias[gcol + 1];
                *(float2*)&C[(size_t)grow * DM + gcol] =
                    make_float2(acc[mt][nt][0] + bx, acc[mt][nt][1] + by);
                *(float2*)&C[(size_t)(grow + 8) * DM + gcol] =
                    make_float2(acc[mt][nt][2] + bx, acc[mt][nt][3] + by);
            }
        }
    }
}

// Persistent fused Q/K/V projection: 1536 items.
__global__ __launch_bounds__(256, 2)
void gemm_qkv_kernel(const __half* __restrict__ xh, float qscale)
{
    extern __shared__ __align__(128) char smem[];
    for (int it = blockIdx.x; it < 1536; it += gridDim.x) {
        const int z = it / 512;
        const int r = it % 512;
        const int row0 = (r >> 3) * GBM;
        const int col0 = (r & 7) * GBN;
        const __half* B = (z == 0) ? g_wq : (z == 1) ? g_wk : g_wv;
        __half* Ch = (z == 0) ? g_qh : (z == 1) ? g_kh : g_vh;
        const float cs = (z == 0) ? qscale : 1.0f;
        gemm_item(xh, B, nullptr, nullptr, Ch, cs, row0, col0, smem);
    }
}

// Persistent output projection: 512 items.
__global__ __launch_bounds__(256, 2)
void gemm_out_kernel(const __half* __restrict__ Ah, float* __restrict__ C,
                     const float* __restrict__ bias)
{
    extern __shared__ __align__(128) char smem[];
    for (int it = blockIdx.x; it < 512; it += gridDim.x) {
        const int row0 = (it >> 3) * GBM;
        const int col0 = (it & 7) * GBN;
        gemm_item(Ah, g_wo, C, bias, nullptr, 1.0f, row0, col0, smem);
    }
}

// ---------------- fp16 flash attention (R15 form: non-persistent) ----------------
#define FA_BN 64
#define FA_TILEB (FA_BN * 128)        // 8192
#define FA_STAGE (2 * FA_TILEB)       // 16384: K | V
#define FA_SMEM (2 * FA_STAGE)        // 32768

__device__ __forceinline__ void attn_prefetch(
    uint32_t stage_base, const __half* K, const __half* V,
    size_t rowbase, int colbase, int key0, int tid)
{
    #pragma unroll
    for (int i = 0; i < 2; ++i) {
        int u = tid + i * 256;
        int r = u >> 3, c = u & 7;
        const size_t g = (rowbase + key0 + r) * DM + colbase + c * 8;
        const uint32_t so = fsw(r, c);
        CP_ASYNC16(stage_base + so,            K + g);
        CP_ASYNC16(stage_base + FA_TILEB + so, V + g);
    }
}

__global__ __launch_bounds__(256, 2)
void attn_mma_kernel(const __half* __restrict__ Q, const __half* __restrict__ K,
                     const __half* __restrict__ V, __half* __restrict__ O)
{
    extern __shared__ __align__(128) char sm[];
    const uint32_t sb = smem_u32(sm);

    const int tid  = threadIdx.x;
    const int warp = tid >> 5;
    const int lane = tid & 31;
    const int sub  = lane >> 3;
    const int l7   = lane & 7;
    const int h = blockIdx.y;
    const int b = blockIdx.z;
    const int q0 = blockIdx.x * 128;

    const size_t rowbase = (size_t)b * T_SZ;
    const int    colbase = h * HD;

    // stage Q tile (128 x 64 fp16) through buffer 0, keep A fragments
    uint32_t qf[4][4];
    {
        #pragma unroll
        for (int i = 0; i < 4; ++i) {
            int u = tid + i * 256;
            int r = u >> 3, c = u & 7;
            const uint4 v = *(const uint4*)(Q + (rowbase + q0 + r) * DM + colbase + c * 8);
            *(uint4*)(sm + fsw(r, c)) = v;
        }
        __syncthreads();
        #pragma unroll
        for (int t = 0; t < 4; ++t) {
            const int r  = warp * 16 + ((sub & 1) << 3) + l7;
            const int ch = t * 2 + (sub >> 1);
            LDSM_X4(qf[t], sb + fsw(r, ch));
        }
        __syncthreads();
    }

    float acc[8][4];
    #pragma unroll
    for (int j = 0; j < 8; ++j)
        #pragma unroll
        for (int c = 0; c < 4; ++c) acc[j][c] = 0.f;
    float m0 = -1e30f, m1 = -1e30f, l0 = 0.f, l1 = 0.f;

    attn_prefetch(sb, K, V, rowbase, colbase, 0, tid);
    CP_COMMIT();

    const int ntiles = T_SZ / FA_BN;   // 32
    for (int kt = 0; kt < ntiles; ++kt) {
        const int s = kt & 1;
        if (kt + 1 < ntiles) {
            attn_prefetch(sb + (1 - s) * FA_STAGE, K, V, rowbase, colbase, (kt + 1) * FA_BN, tid);
            CP_COMMIT();
            CP_WAIT1();
        } else {
            CP_WAIT0();
        }
        __syncthreads();
        const uint32_t ss = sb + s * FA_STAGE;

        // S = Q K^T
        float st[8][4];
        #pragma unroll
        for (int j = 0; j < 8; ++j)
            #pragma unroll
            for (int c = 0; c < 4; ++c) st[j][c] = 0.f;

        #pragma unroll
        for (int np = 0; np < 4; ++np) {
            #pragma unroll
            for (int t = 0; t < 4; ++t) {
                const int r  = np * 16 + ((sub >> 1) << 3) + l7;
                const int ch = t * 2 + (sub & 1);
                uint32_t e[4];
                LDSM_X4(e, ss + fsw(r, ch));
                MMA_F16(st[np*2],   qf[t], e[0], e[1]);
                MMA_F16(st[np*2+1], qf[t], e[2], e[3]);
            }
        }

        // online softmax (log2 domain; Q pre-scaled by 0.125*log2e)
        float tm0 = st[0][0], tm1 = st[0][2];
        #pragma unroll
        for (int j = 0; j < 8; ++j) {
            tm0 = fmaxf(tm0, fmaxf(st[j][0], st[j][1]));
            tm1 = fmaxf(tm1, fmaxf(st[j][2], st[j][3]));
        }
        tm0 = fmaxf(tm0, __shfl_xor_sync(0xffffffffu, tm0, 1));
        tm0 = fmaxf(tm0, __shfl_xor_sync(0xffffffffu, tm0, 2));
        tm1 = fmaxf(tm1, __shfl_xor_sync(0xffffffffu, tm1, 1));
        tm1 = fmaxf(tm1, __shfl_xor_sync(0xffffffffu, tm1, 2));
        const float nm0 = fmaxf(m0, tm0), nm1 = fmaxf(m1, tm1);
        const float c0 = exp2f(m0 - nm0), c1 = exp2f(m1 - nm1);
        m0 = nm0; m1 = nm1;
        if (__any_sync(0xffffffffu, (c0 != 1.f) | (c1 != 1.f))) {
            l0 *= c0; l1 *= c1;
            #pragma unroll
            for (int j = 0; j < 8; ++j) {
                acc[j][0] *= c0; acc[j][1] *= c0;
                acc[j][2] *= c1; acc[j][3] *= c1;
            }
        }
        #pragma unroll
        for (int j = 0; j < 8; ++j) {
            st[j][0] = exp2f(st[j][0] - m0);
            st[j][1] = exp2f(st[j][1] - m0);
            st[j][2] = exp2f(st[j][2] - m1);
            st[j][3] = exp2f(st[j][3] - m1);
            l0 += st[j][0] + st[j][1];
            l1 += st[j][2] + st[j][3];
        }

        // pack P into fp16 A fragments
        uint32_t pf[4][4];
        #pragma unroll
        for (int t = 0; t < 4; ++t) {
            pf[t][0] = pack_h2(st[2*t][0],   st[2*t][1]);
            pf[t][1] = pack_h2(st[2*t][2],   st[2*t][3]);
            pf[t][2] = pack_h2(st[2*t+1][0], st[2*t+1][1]);
            pf[t][3] = pack_h2(st[2*t+1][2], st[2*t+1][3]);
        }

        // acc += P V
        #pragma unroll
        for (int t = 0; t < 4; ++t) {
            #pragma unroll
            for (int dp = 0; dp < 4; ++dp) {
                const int r  = t * 16 + ((sub & 1) << 3) + l7;
                const int ch = dp * 2 + (sub >> 1);
                uint32_t v[4];
                LDSM_X4_T(v, ss + FA_TILEB + fsw(r, ch));
                MMA_F16(acc[dp*2],   pf[t], v[0], v[1]);
                MMA_F16(acc[dp*2+1], pf[t], v[2], v[3]);
            }
        }
        __syncthreads();
    }

    // finalize, write fp16 O
    l0 += __shfl_xor_sync(0xffffffffu, l0, 1);
    l0 += __shfl_xor_sync(0xffffffffu, l0, 2);
    l1 += __shfl_xor_sync(0xffffffffu, l1, 1);
    l1 += __shfl_xor_sync(0xffffffffu, l1, 2);
    const float inv0 = 1.f / (l0 + 1e-8f);
    const float inv1 = 1.f / (l1 + 1e-8f);

    const int r0 = q0 + warp * 16 + (lane >> 2);
    const int ec = (lane & 3) * 2;
    #pragma unroll
    for (int j = 0; j < 8; ++j) {
        const int gcol = colbase + j * 8 + ec;
        *(uint32_t*)&O[(rowbase + r0) * DM + gcol] =
            pack_h2(acc[j][0] * inv0, acc[j][1] * inv0);
        *(uint32_t*)&O[(rowbase + r0 + 8) * DM + gcol] =
            pack_h2(acc[j][2] * inv1, acc[j][3] * inv1);
    }
}

// ---------------- launch ----------------
extern "C" void kernel_launch(void* const* d_in, const int* in_sizes, int n_in,
                              void* d_out, int out_size)
{
    const float* x  = (const float*)d_in[0];
    const float* Wq = (const float*)d_in[1];
    const float* Wk = (const float*)d_in[2];
    const float* Wv = (const float*)d_in[3];
    const float* Wo = (const float*)d_in[4];
    const float* bo = (const float*)d_in[5];
    float* out = (float*)d_out;

    __half *xh, *oh, *qh, *kh, *vh;
    cudaGetSymbolAddress((void**)&xh, g_xh);
    cudaGetSymbolAddress((void**)&oh, g_oh);
    cudaGetSymbolAddress((void**)&qh, g_qh);
    cudaGetSymbolAddress((void**)&kh, g_kh);
    cudaGetSymbolAddress((void**)&vh, g_vh);

    cudaFuncSetAttribute(gemm_qkv_kernel, cudaFuncAttributeMaxDynamicSharedMemorySize, GEMM_SMEM);
    cudaFuncSetAttribute(gemm_out_kernel, cudaFuncAttributeMaxDynamicSharedMemorySize, GEMM_SMEM);
    cudaFuncSetAttribute(attn_mma_kernel, cudaFuncAttributeMaxDynamicSharedMemorySize, FA_SMEM);

    const int n4x = NELEM / 4;
    const int n4w = (DM * DM) / 4;
    cvt_kernel<<<n4x / 256, 256>>>(x, xh, n4x);
    dim3 wgrid(n4w / 256, 1, 4);
    cvtw_kernel<<<wgrid, 256>>>(Wq, Wk, Wv, Wo, n4w);

    const float qscale = 0.125f * 1.44269504088896341f;   // (1/sqrt(64)) * log2(e)
    gemm_qkv_kernel<<<PERSIST_CTAS, 256, GEMM_SMEM>>>(xh, qscale);

    dim3 agrid(T_SZ / 128, NH, B_SZ);       // (16, 16, 4)
    attn_mma_kernel<<<agrid, 256, FA_SMEM>>>(qh, kh, vh, oh);

    gemm_out_kernel<<<PERSIST_CTAS, 256, GEMM_SMEM>>>(oh, out, bo);
}